// round 3
// baseline (speedup 1.0000x reference)
#include <cuda_runtime.h>
#include <cuda_fp16.h>

// CapsuleLayer dynamic routing, recompute architecture (no u_hat materialization).
// B=256, I=16, C=1152, U=10, S=32, J=U*S=320, K1=I*C=18432, 3 iterations.
//
//  prep : xh[b][k]=fp16(x), xhT[k][b]=fp16(x^T), WT[j][k]=W transposed (fp32),
//         bij=0, cij=0.1, A2=0
//  G1   : spart[split][j][b] = partial_k  (cij[c(k),u(j)]*WT[j,k]) * xh[b,k]   (HMMA)
//  squash: v = squash(sum_split spart); writes vh fp16 (iters 1,2) / d_out (iter 3)
//  G2   : Y[j,k'] = sum_b vh[j,b]*xhT[k',b]  fused epilogue:
//         A2[c,u] += sum_{s,i} WT[j,k']*Y[j,k']      (HMMA + atomics)
//  bupd : bij += A2/B ; softmax over u -> cij ; A2=0
//
// Final iteration's agreement pass is skipped (reference discards last b_ij).

#define BB   256
#define CC   1152
#define NU   10
#define SS   32
#define JJ   320
#define IU   16
#define K1   18432
#define SPLIT 32
#define KCHUNK (K1/SPLIT)   // 576
#define KSTEPS (KCHUNK/16)  // 36

// ---- static device scratch ----
__device__ __half d_xh [(size_t)BB * K1];     // 9.4 MB  [b][k], k=i*1152+c
__device__ __half d_xhT[(size_t)K1 * BB];     // 9.4 MB  [k][b]
__device__ float  d_WT [(size_t)JJ * K1];     // 23.6 MB [j][k]
__device__ float  d_spart[(size_t)SPLIT * JJ * BB]; // 10.5 MB
__device__ __half d_vh [JJ * BB];             // 160 KB  [j][b]
__device__ float  d_bij[CC * NU];             // [c][u]
__device__ float  d_cij[NU * CC];             // [u][c]
__device__ float  d_A2 [CC * NU];             // [c][u] agreement accumulator

// ---- helpers ----
__device__ __forceinline__ unsigned pack_h2(float lo, float hi) {
    __half2 h = __floats2half2_rn(lo, hi);
    return *reinterpret_cast<unsigned*>(&h);
}
__device__ __forceinline__ void mma16816(float* d, unsigned a0, unsigned a1,
                                         unsigned a2, unsigned a3,
                                         unsigned b0, unsigned b1) {
    asm volatile(
        "mma.sync.aligned.m16n8k16.row.col.f32.f16.f16.f32 "
        "{%0,%1,%2,%3},{%4,%5,%6,%7},{%8,%9},{%0,%1,%2,%3};"
        : "+f"(d[0]), "+f"(d[1]), "+f"(d[2]), "+f"(d[3])
        : "r"(a0), "r"(a1), "r"(a2), "r"(a3), "r"(b0), "r"(b1));
}

// ---------------------------------------------------------------------------
__global__ void k_prep_init() {
    int t = blockIdx.x * blockDim.x + threadIdx.x;
    if (t < CC * NU) { d_bij[t] = 0.f; d_A2[t] = 0.f; d_cij[t] = 0.1f; }
}

// x [256 b][18432 k] fp32 -> xh fp16 (same layout) + xhT fp16 (transposed)
__global__ void k_prep_x(const float* __restrict__ x) {
    __shared__ float t32[32][33];
    int tx = threadIdx.x, ty = threadIdx.y;
    int k0 = blockIdx.x * 32, b0 = blockIdx.y * 32;
    #pragma unroll
    for (int i = 0; i < 4; i++) {
        int b = b0 + ty + i * 8;
        float v = x[(size_t)b * K1 + k0 + tx];
        t32[ty + i * 8][tx] = v;
        d_xh[(size_t)b * K1 + k0 + tx] = __float2half(v);
    }
    __syncthreads();
    #pragma unroll
    for (int i = 0; i < 4; i++) {
        int k = k0 + ty + i * 8;
        d_xhT[(size_t)k * BB + b0 + tx] = __float2half(t32[tx][ty + i * 8]);
    }
}

// W [1152 c][5120 m] fp32, m=j*16+i  ->  WT[j][i*1152+c] fp32
__global__ void k_prep_w(const float* __restrict__ W) {
    __shared__ float t32[32][33];
    int tx = threadIdx.x, ty = threadIdx.y;
    int m0 = blockIdx.x * 32, c0 = blockIdx.y * 32;
    #pragma unroll
    for (int i = 0; i < 4; i++) {
        int c = c0 + ty + i * 8;
        t32[ty + i * 8][tx] = W[(size_t)c * 5120 + m0 + tx];
    }
    __syncthreads();
    #pragma unroll
    for (int i = 0; i < 4; i++) {
        int m = m0 + ty + i * 8;
        int j = m >> 4, ii = m & 15;
        d_WT[(size_t)j * K1 + ii * CC + c0 + tx] = t32[tx][ty + i * 8];
    }
}

// ---------------------------------------------------------------------------
// G1: spart[split][j][b] = sum_{k in chunk} (cij*WT)[j,k] * xh[b,k]
// grid (10 u-blocks, SPLIT). block 256 = 8 warps (2 m x 4 n), warp tile 16j x 64b.
__global__ void __launch_bounds__(256) k_g1() {
    int tid = threadIdx.x, warp = tid >> 5, lane = tid & 31;
    int g = lane >> 2, t = lane & 3;
    int wm = warp >> 2, wn = warp & 3;
    int u = blockIdx.x;
    int r0 = u * 32 + wm * 16 + g, r1 = r0 + 8;
    int kbase = blockIdx.y * KCHUNK;

    float acc[8][4];
    #pragma unroll
    for (int nf = 0; nf < 8; nf++)
        #pragma unroll
        for (int q = 0; q < 4; q++) acc[nf][q] = 0.f;

    const float* wr0 = d_WT + (size_t)r0 * K1;
    const float* wr1 = d_WT + (size_t)r1 * K1;
    const float* cu  = d_cij + u * CC;
    int c0 = kbase % CC;

    #pragma unroll 2
    for (int step = 0; step < KSTEPS; step++) {
        int k0 = kbase + step * 16;
        float2 cl  = *(const float2*)(cu + c0 + 2 * t);
        float2 ch  = *(const float2*)(cu + c0 + 2 * t + 8);
        float2 w0l = *(const float2*)(wr0 + k0 + 2 * t);
        float2 w0h = *(const float2*)(wr0 + k0 + 2 * t + 8);
        float2 w1l = *(const float2*)(wr1 + k0 + 2 * t);
        float2 w1h = *(const float2*)(wr1 + k0 + 2 * t + 8);
        unsigned a0 = pack_h2(w0l.x * cl.x, w0l.y * cl.y);
        unsigned a1 = pack_h2(w1l.x * cl.x, w1l.y * cl.y);
        unsigned a2 = pack_h2(w0h.x * ch.x, w0h.y * ch.y);
        unsigned a3 = pack_h2(w1h.x * ch.x, w1h.y * ch.y);
        #pragma unroll
        for (int nf = 0; nf < 8; nf++) {
            int bq = wn * 64 + nf * 8 + g;
            const unsigned* xr = (const unsigned*)(d_xh + (size_t)bq * K1 + k0);
            mma16816(acc[nf], a0, a1, a2, a3, xr[t], xr[t + 4]);
        }
        c0 += 16; if (c0 >= CC) c0 -= CC;
    }

    size_t base = (size_t)blockIdx.y * JJ * BB;
    #pragma unroll
    for (int nf = 0; nf < 8; nf++) {
        int bc = wn * 64 + nf * 8 + 2 * t;
        *(float2*)&d_spart[base + (size_t)r0 * BB + bc] = make_float2(acc[nf][0], acc[nf][1]);
        *(float2*)&d_spart[base + (size_t)r1 * BB + bc] = make_float2(acc[nf][2], acc[nf][3]);
    }
}

// ---------------------------------------------------------------------------
// squash: grid (32 s), 512 threads. Reduces SPLIT partials, squashes over u.
__global__ void __launch_bounds__(512) k_squash(float* __restrict__ out, int final_it) {
    __shared__ float sv[NU][BB];
    __shared__ float qp[2][BB];
    int s = blockIdx.x;
    int h = threadIdx.x >> 8, b = threadIdx.x & 255;
    float q = 0.f;
    for (int uu = 0; uu < 5; uu++) {
        int u = h * 5 + uu;
        size_t base = (size_t)(u * 32 + s) * BB + b;
        float v = 0.f;
        #pragma unroll
        for (int p = 0; p < SPLIT; p++) v += d_spart[(size_t)p * JJ * BB + base];
        sv[u][b] = v;
        q = fmaf(v, v, q);
    }
    qp[h][b] = q;
    __syncthreads();
    if (h == 0) {
        float Q = qp[0][b] + qp[1][b];
        float mag = sqrtf(Q);
        float f = Q / ((1.f + Q) * mag);
        #pragma unroll
        for (int u = 0; u < NU; u++) {
            float v = sv[u][b] * f;
            int j = u * 32 + s;
            if (final_it) out[b * JJ + j] = v;
            else          d_vh[j * BB + b] = __float2half(v);
        }
    }
}

// ---------------------------------------------------------------------------
// G2: agreement. grid 288 (k'-tiles of 64). block 256 = 8 warps, warp tile 32s x 8k'.
// Y = vh @ xhT, epilogue multiplies by WT and reduces into A2[c][u] atomically.
__global__ void __launch_bounds__(256) k_g2() {
    __shared__ __half xs[64][264];   // [k'_local][b], padded stride
    int tid = threadIdx.x, warp = tid >> 5, lane = tid & 31;
    int g = lane >> 2, t = lane & 3;
    int kp0 = blockIdx.x * 64;

    // stage xhT slice: 64 rows x 256 halfs
    for (int i = tid; i < 64 * 128; i += 256) {
        int r = i >> 7, cidx = i & 127;
        ((unsigned*)&xs[r][0])[cidx] =
            ((const unsigned*)(d_xhT + (size_t)(kp0 + r) * BB))[cidx];
    }
    __syncthreads();

    int n0 = warp * 8;
    int cbase = (kp0 % CC) + n0;
    const unsigned* bs = (const unsigned*)&xs[n0 + g][0];

    for (int u = 0; u < NU; u++) {
        float acc0[4] = {0.f, 0.f, 0.f, 0.f};
        float acc1[4] = {0.f, 0.f, 0.f, 0.f};
        const unsigned* v0 = (const unsigned*)(d_vh + (u * 32 + g)      * BB);
        const unsigned* v1 = (const unsigned*)(d_vh + (u * 32 + 8 + g)  * BB);
        const unsigned* v2 = (const unsigned*)(d_vh + (u * 32 + 16 + g) * BB);
        const unsigned* v3 = (const unsigned*)(d_vh + (u * 32 + 24 + g) * BB);
        #pragma unroll
        for (int kb = 0; kb < 16; kb++) {
            unsigned b0 = bs[kb * 8 + t], b1 = bs[kb * 8 + t + 4];
            mma16816(acc0, v0[kb * 8 + t], v1[kb * 8 + t],
                           v0[kb * 8 + t + 4], v1[kb * 8 + t + 4], b0, b1);
            mma16816(acc1, v2[kb * 8 + t], v3[kb * 8 + t],
                           v2[kb * 8 + t + 4], v3[kb * 8 + t + 4], b0, b1);
        }
        // epilogue: multiply by WT, reduce over s (rows), atomically add to A2
        const float* wbase = d_WT + (size_t)(u * 32) * K1 + kp0 + n0 + 2 * t;
        float2 wg   = *(const float2*)(wbase + (size_t)g        * K1);
        float2 wg8  = *(const float2*)(wbase + (size_t)(g + 8)  * K1);
        float2 wg16 = *(const float2*)(wbase + (size_t)(g + 16) * K1);
        float2 wg24 = *(const float2*)(wbase + (size_t)(g + 24) * K1);
        float p0 = acc0[0] * wg.x + acc0[2] * wg8.x + acc1[0] * wg16.x + acc1[2] * wg24.x;
        float p1 = acc0[1] * wg.y + acc0[3] * wg8.y + acc1[1] * wg16.y + acc1[3] * wg24.y;
        #pragma unroll
        for (int m = 4; m <= 16; m <<= 1) {
            p0 += __shfl_xor_sync(0xffffffffu, p0, m);
            p1 += __shfl_xor_sync(0xffffffffu, p1, m);
        }
        if (lane < 4) {
            atomicAdd(&d_A2[(cbase + 2 * t)     * NU + u], p0);
            atomicAdd(&d_A2[(cbase + 2 * t + 1) * NU + u], p1);
        }
    }
}

// ---------------------------------------------------------------------------
__global__ void k_bupd() {
    int c = blockIdx.x * blockDim.x + threadIdx.x;
    if (c >= CC) return;
    float bv[NU], m = -1e30f;
    #pragma unroll
    for (int u = 0; u < NU; u++) {
        float a = d_A2[c * NU + u];
        d_A2[c * NU + u] = 0.f;
        float nb = d_bij[c * NU + u] + a * (1.f / BB);
        d_bij[c * NU + u] = nb;
        bv[u] = nb;
        m = fmaxf(m, nb);
    }
    float den = 0.f;
    #pragma unroll
    for (int u = 0; u < NU; u++) { bv[u] = expf(bv[u] - m); den += bv[u]; }
    float inv = 1.f / den;
    #pragma unroll
    for (int u = 0; u < NU; u++) d_cij[u * CC + c] = bv[u] * inv;
}

// ---------------------------------------------------------------------------
extern "C" void kernel_launch(void* const* d_in, const int* in_sizes, int n_in,
                              void* d_out, int out_size) {
    const float* x = (const float*)d_in[0];
    const float* W = (const float*)d_in[1];
    if (n_in >= 2 && in_sizes[0] == CC * NU * SS * IU && in_sizes[1] == BB * IU * CC) {
        const float* tmp = x; x = W; W = tmp;
    }
    float* out = (float*)d_out;

    k_prep_init<<<(CC * NU + 255) / 256, 256>>>();
    k_prep_x<<<dim3(K1 / 32, BB / 32), dim3(32, 8)>>>(x);
    k_prep_w<<<dim3(5120 / 32, CC / 32), dim3(32, 8)>>>(W);

    // iteration 1
    k_g1<<<dim3(NU, SPLIT), 256>>>();
    k_squash<<<SS, 512>>>(out, 0);
    k_g2<<<K1 / 64, 256>>>();
    k_bupd<<<(CC + 255) / 256, 256>>>();
    // iteration 2
    k_g1<<<dim3(NU, SPLIT), 256>>>();
    k_squash<<<SS, 512>>>(out, 0);
    k_g2<<<K1 / 64, 256>>>();
    k_bupd<<<(CC + 255) / 256, 256>>>();
    // iteration 3 (agreement discarded by reference)
    k_g1<<<dim3(NU, SPLIT), 256>>>();
    k_squash<<<SS, 512>>>(out, 1);
}

// round 4
// speedup vs baseline: 2.7065x; 2.7065x over previous
#include <cuda_runtime.h>
#include <cuda_fp16.h>
#include <stdint.h>

// CapsuleLayer dynamic routing: recompute architecture, smem-staged HMMA GEMMs.
// B=256, I=16, C=1152, U=10, S=32, J=320, K1=18432, 3 iterations.

#define BB   256
#define CC   1152
#define NU   10
#define SS   32
#define JJ   320
#define K1   18432
#define SPLIT 36
#define KCHUNK 512          // K1/SPLIT
#define NSTG  16            // KCHUNK/32
#define ASTR  40            // A smem stride (halfs): 80B, conflict-free for ldmatrix
#define BSTR  264           // B smem stride (halfs): 528B ≡ 16 (mod 128) conflict-free

// ---- static device scratch ----
__device__ __half d_xhT[(size_t)K1 * BB];          // 9.4 MB  [k][b]
__device__ float  d_WT [(size_t)JJ * K1];          // 23.6 MB [j][k], k=i*1152+c
__device__ float  d_spart[(size_t)SPLIT * JJ * BB];// 11.8 MB
__device__ __half d_vh [JJ * BB];                  // [j][b]
__device__ float  d_bij[CC * NU];
__device__ float  d_cij[NU * CC];                  // [u][c]
__device__ float  d_A2 [CC * NU];

// ---- mma / ldmatrix helpers ----
__device__ __forceinline__ void mma16816(float* d, uint32_t a0, uint32_t a1,
                                         uint32_t a2, uint32_t a3,
                                         uint32_t b0, uint32_t b1) {
    asm volatile(
        "mma.sync.aligned.m16n8k16.row.col.f32.f16.f16.f32 "
        "{%0,%1,%2,%3},{%4,%5,%6,%7},{%8,%9},{%0,%1,%2,%3};"
        : "+f"(d[0]), "+f"(d[1]), "+f"(d[2]), "+f"(d[3])
        : "r"(a0), "r"(a1), "r"(a2), "r"(a3), "r"(b0), "r"(b1));
}
__device__ __forceinline__ uint32_t cvta_s(const void* p) {
    return (uint32_t)__cvta_generic_to_shared(p);
}
__device__ __forceinline__ void ldsm_x4(uint32_t* r, uint32_t addr) {
    asm volatile("ldmatrix.sync.aligned.m8n8.x4.shared.b16 {%0,%1,%2,%3},[%4];"
                 : "=r"(r[0]), "=r"(r[1]), "=r"(r[2]), "=r"(r[3]) : "r"(addr));
}
__device__ __forceinline__ void ldsm_x4_t(uint32_t* r, uint32_t addr) {
    asm volatile("ldmatrix.sync.aligned.m8n8.x4.trans.shared.b16 {%0,%1,%2,%3},[%4];"
                 : "=r"(r[0]), "=r"(r[1]), "=r"(r[2]), "=r"(r[3]) : "r"(addr));
}
__device__ __forceinline__ uint32_t h2u(__half2 h) {
    return *reinterpret_cast<uint32_t*>(&h);
}

// ---------------------------------------------------------------------------
__global__ void k_prep_init() {
    int t = blockIdx.x * blockDim.x + threadIdx.x;
    if (t < CC * NU) { d_bij[t] = 0.f; d_A2[t] = 0.f; d_cij[t] = 0.1f; }
}

// x [256 b][18432 k] fp32 -> xhT [k][b] fp16
__global__ void k_prep_x(const float* __restrict__ x) {
    __shared__ float t32[32][33];
    int tx = threadIdx.x, ty = threadIdx.y;
    int k0 = blockIdx.x * 32, b0 = blockIdx.y * 32;
    #pragma unroll
    for (int i = 0; i < 4; i++)
        t32[ty + i * 8][tx] = x[(size_t)(b0 + ty + i * 8) * K1 + k0 + tx];
    __syncthreads();
    #pragma unroll
    for (int i = 0; i < 4; i++) {
        int k = k0 + ty + i * 8;
        d_xhT[(size_t)k * BB + b0 + tx] = __float2half(t32[tx][ty + i * 8]);
    }
}

// W [1152 c][5120 m], m=j*16+i  ->  WT[j][i*1152+c] fp32
__global__ void k_prep_w(const float* __restrict__ W) {
    __shared__ float t32[32][33];
    int tx = threadIdx.x, ty = threadIdx.y;
    int m0 = blockIdx.x * 32, c0 = blockIdx.y * 32;
    #pragma unroll
    for (int i = 0; i < 4; i++)
        t32[ty + i * 8][tx] = W[(size_t)(c0 + ty + i * 8) * 5120 + m0 + tx];
    __syncthreads();
    #pragma unroll
    for (int i = 0; i < 4; i++) {
        int m = m0 + ty + i * 8;
        int j = m >> 4, ii = m & 15;
        d_WT[(size_t)j * K1 + ii * CC + c0 + tx] = t32[tx][ty + i * 8];
    }
}

// ---------------------------------------------------------------------------
// G1: spart[split][j][b] = sum_{k in chunk} (cij[u(j),c(k)]*WT[j,k]) * x[b,k]
// grid (5 m-tiles, 36 splits), block 256 = 8 warps (2m x 4n), warp 32j x 64b.
__global__ void __launch_bounds__(256) k_g1() {
    __shared__ __align__(16) __half a_s[2][64 * ASTR];   // 10 KB
    __shared__ __align__(16) __half b_s[2][32 * BSTR];   // 33 KB

    const int tid = threadIdx.x;
    const int j0 = blockIdx.x * 64;
    const int kbase = blockIdx.y * KCHUNK;
    const int warp = tid >> 5, lane = tid & 31;
    const int wm = warp >> 2, wn = warp & 3;
    const int m0 = wm * 32, n0 = wn * 64;
    const int lt = lane >> 3, lr = lane & 7;
    const int g = lane >> 2, t = lane & 3;

    // A staging: thread -> row ar (j), quarter aq (8 k each)
    const int ar = tid >> 2, aq = tid & 3;
    const int u_st = (j0 + ar) >> 5;
    const float* wrow = d_WT + (size_t)(j0 + ar) * K1;
    const float* crow = d_cij + u_st * CC;

    // ldmatrix per-lane offsets (halfs*2 = bytes)
    const uint32_t aoff = (uint32_t)((((lt & 1) * 8 + lr) * ASTR + (lt >> 1) * 8) * 2);
    const uint32_t boff = (uint32_t)((((lt & 1) * 8 + lr) * BSTR + (lt >> 1) * 8) * 2);
    uint32_t abase[2] = {cvta_s(&a_s[0][0]), cvta_s(&a_s[1][0])};
    uint32_t bbase[2] = {cvta_s(&b_s[0][0]), cvta_s(&b_s[1][0])};

    float acc[2][8][4];
    #pragma unroll
    for (int mb = 0; mb < 2; mb++)
        #pragma unroll
        for (int nb = 0; nb < 8; nb++)
            #pragma unroll
            for (int q = 0; q < 4; q++) acc[mb][nb][q] = 0.f;

    uint4 areg;        // 8 scaled halves
    uint4 breg[4];     // B tile slice

    // ---- load stage s into regs ----
    auto load_stage = [&](int s) {
        int k0 = kbase + s * 32;
        int c0 = k0 % CC;          // 32-aligned, no wrap within stage
        float4 w0 = *(const float4*)(wrow + k0 + aq * 8);
        float4 w1 = *(const float4*)(wrow + k0 + aq * 8 + 4);
        float4 cA = *(const float4*)(crow + c0 + aq * 8);
        float4 cB = *(const float4*)(crow + c0 + aq * 8 + 4);
        areg.x = h2u(__floats2half2_rn(w0.x * cA.x, w0.y * cA.y));
        areg.y = h2u(__floats2half2_rn(w0.z * cA.z, w0.w * cA.w));
        areg.z = h2u(__floats2half2_rn(w1.x * cB.x, w1.y * cB.y));
        areg.w = h2u(__floats2half2_rn(w1.z * cB.z, w1.w * cB.w));
        #pragma unroll
        for (int jj = 0; jj < 4; jj++) {
            int r = warp + jj * 8;
            breg[jj] = *(const uint4*)(d_xhT + (size_t)(k0 + r) * BB + lane * 8);
        }
    };
    auto store_stage = [&](int buf) {
        *(uint4*)&a_s[buf][ar * ASTR + aq * 8] = areg;
        #pragma unroll
        for (int jj = 0; jj < 4; jj++)
            *(uint4*)&b_s[buf][(warp + jj * 8) * BSTR + lane * 8] = breg[jj];
    };

    load_stage(0);
    store_stage(0);
    __syncthreads();

    for (int s = 0; s < NSTG; s++) {
        int buf = s & 1;
        if (s + 1 < NSTG) load_stage(s + 1);

        #pragma unroll
        for (int kk = 0; kk < 32; kk += 16) {
            uint32_t A0[4], A1[4], bf[8][2], rr[4];
            ldsm_x4(A0, abase[buf] + (uint32_t)((m0 * ASTR + kk) * 2) + aoff);
            ldsm_x4(A1, abase[buf] + (uint32_t)(((m0 + 16) * ASTR + kk) * 2) + aoff);
            #pragma unroll
            for (int i = 0; i < 4; i++) {
                ldsm_x4_t(rr, bbase[buf] + (uint32_t)((kk * BSTR + n0 + i * 16) * 2) + boff);
                bf[2 * i][0] = rr[0]; bf[2 * i][1] = rr[1];
                bf[2 * i + 1][0] = rr[2]; bf[2 * i + 1][1] = rr[3];
            }
            #pragma unroll
            for (int nb = 0; nb < 8; nb++) {
                mma16816(acc[0][nb], A0[0], A0[1], A0[2], A0[3], bf[nb][0], bf[nb][1]);
                mma16816(acc[1][nb], A1[0], A1[1], A1[2], A1[3], bf[nb][0], bf[nb][1]);
            }
        }
        __syncthreads();
        if (s + 1 < NSTG) {
            store_stage(buf ^ 1);
            __syncthreads();
        }
    }

    size_t base = (size_t)blockIdx.y * JJ * BB;
    #pragma unroll
    for (int mb = 0; mb < 2; mb++)
        #pragma unroll
        for (int nb = 0; nb < 8; nb++) {
            int j = j0 + m0 + mb * 16 + g;
            int b = n0 + nb * 8 + 2 * t;
            *(float2*)&d_spart[base + (size_t)j * BB + b] =
                make_float2(acc[mb][nb][0], acc[mb][nb][1]);
            *(float2*)&d_spart[base + (size_t)(j + 8) * BB + b] =
                make_float2(acc[mb][nb][2], acc[mb][nb][3]);
        }
}

// ---------------------------------------------------------------------------
// squash: grid (32 s), 512 threads.
__global__ void __launch_bounds__(512) k_squash(float* __restrict__ out, int final_it) {
    __shared__ float sv[NU][BB];
    __shared__ float qp[2][BB];
    int s = blockIdx.x;
    int h = threadIdx.x >> 8, b = threadIdx.x & 255;
    float q = 0.f;
    for (int uu = 0; uu < 5; uu++) {
        int u = h * 5 + uu;
        size_t base = (size_t)(u * 32 + s) * BB + b;
        float v = 0.f;
        #pragma unroll
        for (int p = 0; p < SPLIT; p++) v += d_spart[(size_t)p * JJ * BB + base];
        sv[u][b] = v;
        q = fmaf(v, v, q);
    }
    qp[h][b] = q;
    __syncthreads();
    if (h == 0) {
        float Q = qp[0][b] + qp[1][b];
        float mag = sqrtf(Q);
        float f = Q / ((1.f + Q) * mag);
        #pragma unroll
        for (int u = 0; u < NU; u++) {
            float v = sv[u][b] * f;
            int j = u * 32 + s;
            if (final_it) out[b * JJ + j] = v;
            else          d_vh[j * BB + b] = __float2half(v);
        }
    }
}

// ---------------------------------------------------------------------------
// G2: A2[c,u] += sum_j WT[j,k'] * (sum_b vh[j,b]*x[k',b]).
// grid 144 (128 k' each), block 256 = 8 warps (2 j-warps x 4 k'-warps).
// dynamic smem: xs[128][BSTR] + vs[32][BSTR].
__global__ void __launch_bounds__(256) k_g2() {
    extern __shared__ __align__(16) __half sm2[];
    __half* xs = sm2;                     // [128][BSTR]
    __half* vs = sm2 + 128 * BSTR;        // [32][BSTR]

    const int tid = threadIdx.x, warp = tid >> 5, lane = tid & 31;
    const int wm = warp >> 2, wn = warp & 3;
    const int lt = lane >> 3, lr = lane & 7;
    const int g = lane >> 2, t = lane & 3;
    const int kp0 = blockIdx.x * 128;
    const int cb = kp0 % CC;

    // stage xs: 128 rows x 512B (coalesced)
    #pragma unroll
    for (int it = 0; it < 16; it++) {
        int idx = tid + it * 256;
        int r = idx >> 5, col = idx & 31;
        *(uint4*)&xs[r * BSTR + col * 8] =
            *(const uint4*)(d_xhT + (size_t)(kp0 + r) * BB + col * 8);
    }

    const uint32_t vbase = cvta_s(vs), xbase = cvta_s(xs);
    // A frag lane offset (rows = j), B frag lane offset (rows = k')
    const uint32_t aoff = (uint32_t)(((wm * 16 + (lt & 1) * 8 + lr) * BSTR + (lt >> 1) * 8) * 2);
    const uint32_t boffc = (uint32_t)((((lt >> 1) * 8 + lr) * BSTR + (lt & 1) * 8) * 2);

    for (int u = 0; u < NU; u++) {
        __syncthreads();   // xs ready (u=0) / prev-u readers of vs done
        #pragma unroll
        for (int it = 0; it < 4; it++) {
            int idx = tid + it * 256;
            int r = idx >> 5, col = idx & 31;
            *(uint4*)&vs[r * BSTR + col * 8] =
                *(const uint4*)(d_vh + (size_t)(u * 32 + r) * BB + col * 8);
        }
        __syncthreads();

        float acc[4][4];
        #pragma unroll
        for (int nb = 0; nb < 4; nb++)
            #pragma unroll
            for (int q = 0; q < 4; q++) acc[nb][q] = 0.f;

        #pragma unroll 4
        for (int kk = 0; kk < 256; kk += 16) {
            uint32_t A[4], bf[4][2], rr[4];
            ldsm_x4(A, vbase + (uint32_t)(kk * 2) + aoff);
            #pragma unroll
            for (int q = 0; q < 2; q++) {
                ldsm_x4(rr, xbase + (uint32_t)(((wn * 32 + q * 16) * BSTR + kk) * 2) + boffc);
                bf[2 * q][0] = rr[0]; bf[2 * q][1] = rr[1];
                bf[2 * q + 1][0] = rr[2]; bf[2 * q + 1][1] = rr[3];
            }
            #pragma unroll
            for (int nb = 0; nb < 4; nb++)
                mma16816(acc[nb], A[0], A[1], A[2], A[3], bf[nb][0], bf[nb][1]);
        }

        // epilogue: multiply by WT, reduce over j, atomics into A2
        int jA = u * 32 + wm * 16 + g;
        const float* wrow = d_WT + (size_t)jA * K1;
        #pragma unroll
        for (int nb = 0; nb < 4; nb++) {
            int kc = kp0 + wn * 32 + nb * 8 + 2 * t;
            float2 w0 = *(const float2*)(wrow + kc);
            float2 w1 = *(const float2*)(wrow + 8 * (size_t)K1 + kc);
            float p0 = acc[nb][0] * w0.x + acc[nb][2] * w1.x;
            float p1 = acc[nb][1] * w0.y + acc[nb][3] * w1.y;
            #pragma unroll
            for (int m = 4; m <= 16; m <<= 1) {
                p0 += __shfl_xor_sync(0xffffffffu, p0, m);
                p1 += __shfl_xor_sync(0xffffffffu, p1, m);
            }
            if (g == 0) {
                int cc = cb + wn * 32 + nb * 8 + 2 * t;
                atomicAdd(&d_A2[cc * NU + u], p0);
                atomicAdd(&d_A2[(cc + 1) * NU + u], p1);
            }
        }
    }
}

// ---------------------------------------------------------------------------
__global__ void k_bupd() {
    int c = blockIdx.x * blockDim.x + threadIdx.x;
    if (c >= CC) return;
    float bv[NU], m = -1e30f;
    #pragma unroll
    for (int u = 0; u < NU; u++) {
        float a = d_A2[c * NU + u];
        d_A2[c * NU + u] = 0.f;
        float nb = d_bij[c * NU + u] + a * (1.f / BB);
        d_bij[c * NU + u] = nb;
        bv[u] = nb;
        m = fmaxf(m, nb);
    }
    float den = 0.f;
    #pragma unroll
    for (int u = 0; u < NU; u++) { bv[u] = expf(bv[u] - m); den += bv[u]; }
    float inv = 1.f / den;
    #pragma unroll
    for (int u = 0; u < NU; u++) d_cij[u * CC + c] = bv[u] * inv;
}

// ---------------------------------------------------------------------------
#define G2_SMEM ((128 * BSTR + 32 * BSTR) * 2)   // 84480 bytes

extern "C" void kernel_launch(void* const* d_in, const int* in_sizes, int n_in,
                              void* d_out, int out_size) {
    const float* x = (const float*)d_in[0];
    const float* W = (const float*)d_in[1];
    if (n_in >= 2 && in_sizes[0] == CC * NU * SS * 16 && in_sizes[1] == BB * 16 * CC) {
        const float* tmp = x; x = W; W = tmp;
    }
    float* out = (float*)d_out;

    static int attr_done = 0;
    if (!attr_done) {
        cudaFuncSetAttribute(k_g2, cudaFuncAttributeMaxDynamicSharedMemorySize, G2_SMEM);
        attr_done = 1;
    }

    k_prep_init<<<(CC * NU + 255) / 256, 256>>>();
    k_prep_x<<<dim3(K1 / 32, BB / 32), dim3(32, 8)>>>(x);
    k_prep_w<<<dim3(5120 / 32, CC / 32), dim3(32, 8)>>>(W);

    for (int it = 0; it < 3; it++) {
        k_g1<<<dim3(5, SPLIT), 256>>>();
        k_squash<<<SS, 512>>>(out, it == 2);
        if (it < 2) {
            k_g2<<<K1 / 128, 256, G2_SMEM>>>();
            k_bupd<<<(CC + 255) / 256, 256>>>();
        }
    }
}

// round 5
// speedup vs baseline: 3.0366x; 1.1220x over previous
#include <cuda_runtime.h>
#include <cuda_fp16.h>
#include <stdint.h>

// CapsuleLayer dynamic routing: recompute architecture, cp.async HMMA GEMMs, fp16 W.
// B=256, I=16, C=1152, U=10, S=32, J=320, K1=18432, 3 iterations.

#define BB   256
#define CC   1152
#define NU   10
#define SS   32
#define JJ   320
#define K1   18432
#define SPLIT 32
#define KCHUNK 576          // K1/SPLIT
#define NSTG  18            // KCHUNK/32
#define ASTR  40            // A smem stride (halfs)
#define BSTR  264           // B smem stride (halfs): 528B, conflict-free

// ---- static device scratch ----
__device__ __half d_xhT[(size_t)K1 * BB];          // 9.4 MB  [k][b]
__device__ __half d_WTh[(size_t)JJ * K1];          // 11.8 MB [j][k] fp16, k=i*1152+c
__device__ float  d_spart[(size_t)SPLIT * JJ * BB];// 10.5 MB
__device__ __half d_vh [JJ * BB];                  // [j][b]
__device__ float  d_bij[CC * NU];
__device__ float  d_cij[NU * CC];                  // [u][c]
__device__ float  d_A2 [CC * NU];

// ---- helpers ----
__device__ __forceinline__ void mma16816(float* d, uint32_t a0, uint32_t a1,
                                         uint32_t a2, uint32_t a3,
                                         uint32_t b0, uint32_t b1) {
    asm volatile(
        "mma.sync.aligned.m16n8k16.row.col.f32.f16.f16.f32 "
        "{%0,%1,%2,%3},{%4,%5,%6,%7},{%8,%9},{%0,%1,%2,%3};"
        : "+f"(d[0]), "+f"(d[1]), "+f"(d[2]), "+f"(d[3])
        : "r"(a0), "r"(a1), "r"(a2), "r"(a3), "r"(b0), "r"(b1));
}
__device__ __forceinline__ uint32_t cvta_s(const void* p) {
    return (uint32_t)__cvta_generic_to_shared(p);
}
__device__ __forceinline__ void ldsm_x4(uint32_t* r, uint32_t addr) {
    asm volatile("ldmatrix.sync.aligned.m8n8.x4.shared.b16 {%0,%1,%2,%3},[%4];"
                 : "=r"(r[0]), "=r"(r[1]), "=r"(r[2]), "=r"(r[3]) : "r"(addr));
}
__device__ __forceinline__ void ldsm_x4_t(uint32_t* r, uint32_t addr) {
    asm volatile("ldmatrix.sync.aligned.m8n8.x4.trans.shared.b16 {%0,%1,%2,%3},[%4];"
                 : "=r"(r[0]), "=r"(r[1]), "=r"(r[2]), "=r"(r[3]) : "r"(addr));
}
__device__ __forceinline__ uint32_t h2u(__half2 h) {
    return *reinterpret_cast<uint32_t*>(&h);
}
__device__ __forceinline__ void cp16(uint32_t dst, const void* src) {
    asm volatile("cp.async.cg.shared.global [%0], [%1], 16;" :: "r"(dst), "l"(src));
}
__device__ __forceinline__ void cp_commit() {
    asm volatile("cp.async.commit_group;");
}
__device__ __forceinline__ void cp_wait0() {
    asm volatile("cp.async.wait_group 0;");
}

// ---------------------------------------------------------------------------
__global__ void k_prep_init() {
    int t = blockIdx.x * blockDim.x + threadIdx.x;
    if (t < CC * NU) { d_bij[t] = 0.f; d_A2[t] = 0.f; d_cij[t] = 0.1f; }
}

// x [256 b][18432 k] fp32 -> xhT [k][b] fp16
__global__ void k_prep_x(const float* __restrict__ x) {
    __shared__ float t32[32][33];
    int tx = threadIdx.x, ty = threadIdx.y;
    int k0 = blockIdx.x * 32, b0 = blockIdx.y * 32;
    #pragma unroll
    for (int i = 0; i < 4; i++)
        t32[ty + i * 8][tx] = x[(size_t)(b0 + ty + i * 8) * K1 + k0 + tx];
    __syncthreads();
    #pragma unroll
    for (int i = 0; i < 4; i++) {
        int k = k0 + ty + i * 8;
        d_xhT[(size_t)k * BB + b0 + tx] = __float2half(t32[tx][ty + i * 8]);
    }
}

// W [1152 c][5120 m], m=j*16+i  ->  WTh[j][i*1152+c] fp16
__global__ void k_prep_w(const float* __restrict__ W) {
    __shared__ float t32[32][33];
    int tx = threadIdx.x, ty = threadIdx.y;
    int m0 = blockIdx.x * 32, c0 = blockIdx.y * 32;
    #pragma unroll
    for (int i = 0; i < 4; i++)
        t32[ty + i * 8][tx] = W[(size_t)(c0 + ty + i * 8) * 5120 + m0 + tx];
    __syncthreads();
    #pragma unroll
    for (int i = 0; i < 4; i++) {
        int m = m0 + ty + i * 8;
        int j = m >> 4, ii = m & 15;
        d_WTh[(size_t)j * K1 + ii * CC + c0 + tx] = __float2half(t32[tx][ty + i * 8]);
    }
}

// ---------------------------------------------------------------------------
// G1: spart[split][j][b] = sum_{k in chunk} (cij[u(j),c(k)]*W[j,k]) * x[b,k]
// grid (10 j-tiles of 32, 32 splits) = 320 blocks. 8 warps (2m x 4n).
__global__ void __launch_bounds__(256, 3) k_g1() {
    __shared__ __align__(16) __half a_s[2][32 * ASTR];   // 5 KB
    __shared__ __align__(16) __half b_s[2][32 * BSTR];   // 33 KB

    const int tid = threadIdx.x;
    const int j0 = blockIdx.x * 32;
    const int kbase = blockIdx.y * KCHUNK;
    const int warp = tid >> 5, lane = tid & 31;
    const int wm = warp >> 2, wn = warp & 3;
    const int n0 = wn * 64;
    const int lt = lane >> 3, lr = lane & 7;
    const int g = lane >> 2, t = lane & 3;

    // A staging (threads 0..127): row ar (j-local), quarter aq (8 k each)
    const int ar = tid >> 2, aq = tid & 3;
    const int u_st = (j0 + (ar & 31)) >> 5;
    const __half* wrow = d_WTh + (size_t)(j0 + (ar & 31)) * K1;
    const float* crow = d_cij + u_st * CC;

    const uint32_t aoff = (uint32_t)((((lt & 1) * 8 + lr) * ASTR + (lt >> 1) * 8) * 2);
    const uint32_t boff = (uint32_t)((((lt & 1) * 8 + lr) * BSTR + (lt >> 1) * 8) * 2);
    uint32_t abase[2] = {cvta_s(&a_s[0][0]), cvta_s(&a_s[1][0])};
    uint32_t bbase[2] = {cvta_s(&b_s[0][0]), cvta_s(&b_s[1][0])};

    float acc[8][4];
    #pragma unroll
    for (int nb = 0; nb < 8; nb++)
        #pragma unroll
        for (int q = 0; q < 4; q++) acc[nb][q] = 0.f;

    uint4 areg;

    auto loadA = [&](int s) {
        if (tid < 128) {
            int k0 = kbase + s * 32;
            int c0 = k0 % CC;
            uint4 wh = *(const uint4*)(wrow + k0 + aq * 8);
            float4 cA = *(const float4*)(crow + c0 + aq * 8);
            float4 cB = *(const float4*)(crow + c0 + aq * 8 + 4);
            float2 f0 = __half22float2(*(__half2*)&wh.x);
            float2 f1 = __half22float2(*(__half2*)&wh.y);
            float2 f2 = __half22float2(*(__half2*)&wh.z);
            float2 f3 = __half22float2(*(__half2*)&wh.w);
            areg.x = h2u(__floats2half2_rn(f0.x * cA.x, f0.y * cA.y));
            areg.y = h2u(__floats2half2_rn(f1.x * cA.z, f1.y * cA.w));
            areg.z = h2u(__floats2half2_rn(f2.x * cB.x, f2.y * cB.y));
            areg.w = h2u(__floats2half2_rn(f3.x * cB.z, f3.y * cB.w));
        }
    };
    auto storeA = [&](int buf) {
        if (tid < 128) *(uint4*)&a_s[buf][ar * ASTR + aq * 8] = areg;
    };
    auto issueB = [&](int s, int buf) {
        int k0 = kbase + s * 32;
        #pragma unroll
        for (int i = 0; i < 4; i++) {
            int idx = tid + i * 256;
            int r = idx >> 5, seg = idx & 31;
            cp16(bbase[buf] + (uint32_t)((r * BSTR + seg * 8) * 2),
                 d_xhT + (size_t)(k0 + r) * BB + seg * 8);
        }
        cp_commit();
    };

    loadA(0);
    issueB(0, 0);
    storeA(0);
    cp_wait0();
    __syncthreads();

    for (int s = 0; s < NSTG; s++) {
        int buf = s & 1;
        if (s + 1 < NSTG) { loadA(s + 1); issueB(s + 1, buf ^ 1); }

        #pragma unroll
        for (int kk = 0; kk < 32; kk += 16) {
            uint32_t A0[4], rr[4];
            ldsm_x4(A0, abase[buf] + (uint32_t)((wm * 16 * ASTR + kk) * 2) + aoff);
            #pragma unroll
            for (int i = 0; i < 4; i++) {
                ldsm_x4_t(rr, bbase[buf] + (uint32_t)((kk * BSTR + n0 + i * 16) * 2) + boff);
                mma16816(acc[2 * i],     A0[0], A0[1], A0[2], A0[3], rr[0], rr[1]);
                mma16816(acc[2 * i + 1], A0[0], A0[1], A0[2], A0[3], rr[2], rr[3]);
            }
        }
        if (s + 1 < NSTG) {
            storeA(buf ^ 1);
            cp_wait0();
        }
        __syncthreads();
    }

    size_t base = (size_t)blockIdx.y * JJ * BB;
    int j = j0 + wm * 16 + g;
    #pragma unroll
    for (int nb = 0; nb < 8; nb++) {
        int b = n0 + nb * 8 + 2 * t;
        *(float2*)&d_spart[base + (size_t)j * BB + b] = make_float2(acc[nb][0], acc[nb][1]);
        *(float2*)&d_spart[base + (size_t)(j + 8) * BB + b] = make_float2(acc[nb][2], acc[nb][3]);
    }
}

// ---------------------------------------------------------------------------
// squash: grid (32 s), 512 threads.
__global__ void __launch_bounds__(512) k_squash(float* __restrict__ out, int final_it) {
    __shared__ float sv[NU][BB];
    __shared__ float qp[2][BB];
    int s = blockIdx.x;
    int h = threadIdx.x >> 8, b = threadIdx.x & 255;
    float q = 0.f;
    for (int uu = 0; uu < 5; uu++) {
        int u = h * 5 + uu;
        size_t base = (size_t)(u * 32 + s) * BB + b;
        float v = 0.f;
        #pragma unroll
        for (int p = 0; p < SPLIT; p++) v += d_spart[(size_t)p * JJ * BB + base];
        sv[u][b] = v;
        q = fmaf(v, v, q);
    }
    qp[h][b] = q;
    __syncthreads();
    if (h == 0) {
        float Q = qp[0][b] + qp[1][b];
        float mag = sqrtf(Q);
        float f = Q / ((1.f + Q) * mag);
        #pragma unroll
        for (int u = 0; u < NU; u++) {
            float v = sv[u][b] * f;
            int j = u * 32 + s;
            if (final_it) out[b * JJ + j] = v;
            else          d_vh[j * BB + b] = __float2half(v);
        }
    }
}

// ---------------------------------------------------------------------------
// G2: A2[c,u] += sum_j W[j,k'] * (sum_b vh[j,b]*x[k',b]).
// grid 144 (128 k' each), 8 warps (2 j x 4 k'). xs staged once, vs double-buffered.
__global__ void __launch_bounds__(256, 2) k_g2() {
    extern __shared__ __align__(16) __half sm2[];
    __half* xs = sm2;                     // [128][BSTR]
    __half* vs = sm2 + 128 * BSTR;        // [2][32][BSTR]

    const int tid = threadIdx.x, warp = tid >> 5, lane = tid & 31;
    const int wm = warp >> 2, wn = warp & 3;
    const int lt = lane >> 3, lr = lane & 7;
    const int g = lane >> 2, t = lane & 3;
    const int kp0 = blockIdx.x * 128;
    const int cb = kp0 % CC;

    const uint32_t xbase = cvta_s(xs);
    uint32_t vbase[2] = {cvta_s(vs), cvta_s(vs + 32 * BSTR)};

    auto issueV = [&](int u, int buf) {
        #pragma unroll
        for (int i = 0; i < 4; i++) {
            int idx = tid + i * 256;
            int r = idx >> 5, seg = idx & 31;
            cp16(vbase[buf] + (uint32_t)((r * BSTR + seg * 8) * 2),
                 d_vh + (size_t)(u * 32 + r) * BB + seg * 8);
        }
        cp_commit();
    };

    // stage xs (once) + vs(0)
    #pragma unroll
    for (int i = 0; i < 16; i++) {
        int idx = tid + i * 256;
        int r = idx >> 5, seg = idx & 31;
        cp16(xbase + (uint32_t)((r * BSTR + seg * 8) * 2),
             d_xhT + (size_t)(kp0 + r) * BB + seg * 8);
    }
    issueV(0, 0);
    cp_wait0();
    __syncthreads();

    const uint32_t aoff = (uint32_t)(((wm * 16 + (lt & 1) * 8 + lr) * BSTR + (lt >> 1) * 8) * 2);
    const uint32_t boffc = (uint32_t)((((lt >> 1) * 8 + lr) * BSTR + (lt & 1) * 8) * 2);

    for (int u = 0; u < NU; u++) {
        int buf = u & 1;
        if (u + 1 < NU) issueV(u + 1, buf ^ 1);

        float acc[4][4];
        #pragma unroll
        for (int nb = 0; nb < 4; nb++)
            #pragma unroll
            for (int q = 0; q < 4; q++) acc[nb][q] = 0.f;

        #pragma unroll 4
        for (int kk = 0; kk < 256; kk += 16) {
            uint32_t A[4], rr[4];
            ldsm_x4(A, vbase[buf] + (uint32_t)(kk * 2) + aoff);
            #pragma unroll
            for (int q = 0; q < 2; q++) {
                ldsm_x4(rr, xbase + (uint32_t)(((wn * 32 + q * 16) * BSTR + kk) * 2) + boffc);
                mma16816(acc[2 * q],     A[0], A[1], A[2], A[3], rr[0], rr[1]);
                mma16816(acc[2 * q + 1], A[0], A[1], A[2], A[3], rr[2], rr[3]);
            }
        }

        // epilogue: multiply by W (fp16), reduce over j, atomics into A2
        int jA = u * 32 + wm * 16 + g;
        const __half* wrow = d_WTh + (size_t)jA * K1;
        #pragma unroll
        for (int nb = 0; nb < 4; nb++) {
            int kc = kp0 + wn * 32 + nb * 8 + 2 * t;
            float2 w0 = __half22float2(*(const __half2*)(wrow + kc));
            float2 w1 = __half22float2(*(const __half2*)(wrow + 8 * (size_t)K1 + kc));
            float p0 = acc[nb][0] * w0.x + acc[nb][2] * w1.x;
            float p1 = acc[nb][1] * w0.y + acc[nb][3] * w1.y;
            #pragma unroll
            for (int m = 4; m <= 16; m <<= 1) {
                p0 += __shfl_xor_sync(0xffffffffu, p0, m);
                p1 += __shfl_xor_sync(0xffffffffu, p1, m);
            }
            if (g == 0) {
                int cc = cb + wn * 32 + nb * 8 + 2 * t;
                atomicAdd(&d_A2[cc * NU + u], p0);
                atomicAdd(&d_A2[(cc + 1) * NU + u], p1);
            }
        }
        if (u + 1 < NU) cp_wait0();
        __syncthreads();
    }
}

// ---------------------------------------------------------------------------
__global__ void k_bupd() {
    int c = blockIdx.x * blockDim.x + threadIdx.x;
    if (c >= CC) return;
    float bv[NU], m = -1e30f;
    #pragma unroll
    for (int u = 0; u < NU; u++) {
        float a = d_A2[c * NU + u];
        d_A2[c * NU + u] = 0.f;
        float nb = d_bij[c * NU + u] + a * (1.f / BB);
        d_bij[c * NU + u] = nb;
        bv[u] = nb;
        m = fmaxf(m, nb);
    }
    float den = 0.f;
    #pragma unroll
    for (int u = 0; u < NU; u++) { bv[u] = expf(bv[u] - m); den += bv[u]; }
    float inv = 1.f / den;
    #pragma unroll
    for (int u = 0; u < NU; u++) d_cij[u * CC + c] = bv[u] * inv;
}

// ---------------------------------------------------------------------------
#define G2_SMEM ((128 * BSTR + 64 * BSTR) * 2)   // 101376 bytes

extern "C" void kernel_launch(void* const* d_in, const int* in_sizes, int n_in,
                              void* d_out, int out_size) {
    const float* x = (const float*)d_in[0];
    const float* W = (const float*)d_in[1];
    if (n_in >= 2 && in_sizes[0] == CC * NU * SS * 16 && in_sizes[1] == BB * 16 * CC) {
        const float* tmp = x; x = W; W = tmp;
    }
    float* out = (float*)d_out;

    static int attr_done = 0;
    if (!attr_done) {
        cudaFuncSetAttribute(k_g2, cudaFuncAttributeMaxDynamicSharedMemorySize, G2_SMEM);
        attr_done = 1;
    }

    k_prep_init<<<(CC * NU + 255) / 256, 256>>>();
    k_prep_x<<<dim3(K1 / 32, BB / 32), dim3(32, 8)>>>(x);
    k_prep_w<<<dim3(5120 / 32, CC / 32), dim3(32, 8)>>>(W);

    for (int it = 0; it < 3; it++) {
        k_g1<<<dim3(10, SPLIT), 256>>>();
        k_squash<<<SS, 512>>>(out, it == 2);
        if (it < 2) {
            k_g2<<<K1 / 128, 256, G2_SMEM>>>();
            k_bupd<<<(CC + 255) / 256, 256>>>();
        }
    }
}

// round 7
// speedup vs baseline: 3.3649x; 1.1081x over previous
#include <cuda_runtime.h>
#include <cuda_fp16.h>
#include <stdint.h>

// CapsuleLayer dynamic routing: recompute architecture, pipelined HMMA GEMMs.
// B=256, I=16, C=1152, U=10, S=32, J=320, K1=18432, 3 iterations.

#define BB   256
#define CC   1152
#define NU   10
#define SS   32
#define JJ   320
#define K1   18432
#define SPLIT 64
#define KCHUNK 288          // K1/SPLIT
#define NSTG  9             // KCHUNK/32
#define G1STG 3             // pipeline depth
#define ASTR  40            // A smem stride (halfs)
#define BSTR  264           // B smem stride (halfs)
#define BSTR2 136           // G2 smem stride (halfs), 128 data + pad

// ---- static device scratch ----
__device__ __half d_xhT[(size_t)K1 * BB];            // 9.4 MB  [k][b]
__device__ __half d_WTh[(size_t)JJ * K1];            // 11.8 MB [j][k] fp16, k=i*1152+c
__device__ float  d_spart[(size_t)SPLIT * JJ * BB];  // 21 MB
__device__ __half d_vh [JJ * BB];                    // [j][b]
__device__ float  d_bij[CC * NU];
__device__ float  d_cij[NU * CC];                    // [u][c]
__device__ float  d_A2 [CC * NU];

// ---- helpers ----
__device__ __forceinline__ void mma16816(float* d, uint32_t a0, uint32_t a1,
                                         uint32_t a2, uint32_t a3,
                                         uint32_t b0, uint32_t b1) {
    asm volatile(
        "mma.sync.aligned.m16n8k16.row.col.f32.f16.f16.f32 "
        "{%0,%1,%2,%3},{%4,%5,%6,%7},{%8,%9},{%0,%1,%2,%3};"
        : "+f"(d[0]), "+f"(d[1]), "+f"(d[2]), "+f"(d[3])
        : "r"(a0), "r"(a1), "r"(a2), "r"(a3), "r"(b0), "r"(b1));
}
__device__ __forceinline__ uint32_t cvta_s(const void* p) {
    return (uint32_t)__cvta_generic_to_shared(p);
}
__device__ __forceinline__ void ldsm_x4(uint32_t* r, uint32_t addr) {
    asm volatile("ldmatrix.sync.aligned.m8n8.x4.shared.b16 {%0,%1,%2,%3},[%4];"
                 : "=r"(r[0]), "=r"(r[1]), "=r"(r[2]), "=r"(r[3]) : "r"(addr));
}
__device__ __forceinline__ void ldsm_x4_t(uint32_t* r, uint32_t addr) {
    asm volatile("ldmatrix.sync.aligned.m8n8.x4.trans.shared.b16 {%0,%1,%2,%3},[%4];"
                 : "=r"(r[0]), "=r"(r[1]), "=r"(r[2]), "=r"(r[3]) : "r"(addr));
}
__device__ __forceinline__ uint32_t h2u(__half2 h) {
    return *reinterpret_cast<uint32_t*>(&h);
}
__device__ __forceinline__ uint32_t scale_h2(uint32_t a, float2 c) {
    float2 f = __half22float2(*reinterpret_cast<__half2*>(&a));
    return h2u(__floats2half2_rn(f.x * c.x, f.y * c.y));
}
__device__ __forceinline__ void cp16(uint32_t dst, const void* src) {
    asm volatile("cp.async.cg.shared.global [%0], [%1], 16;" :: "r"(dst), "l"(src));
}
__device__ __forceinline__ void cp_commit() { asm volatile("cp.async.commit_group;"); }
__device__ __forceinline__ void cp_wait0() { asm volatile("cp.async.wait_group 0;"); }
__device__ __forceinline__ void cp_wait1() { asm volatile("cp.async.wait_group 1;"); }

// ---------------------------------------------------------------------------
__global__ void k_prep_init() {
    int t = blockIdx.x * blockDim.x + threadIdx.x;
    if (t < CC * NU) { d_bij[t] = 0.f; d_A2[t] = 0.f; d_cij[t] = 0.1f; }
}

__global__ void k_prep_x(const float* __restrict__ x) {
    __shared__ float t32[32][33];
    int tx = threadIdx.x, ty = threadIdx.y;
    int k0 = blockIdx.x * 32, b0 = blockIdx.y * 32;
    #pragma unroll
    for (int i = 0; i < 4; i++)
        t32[ty + i * 8][tx] = x[(size_t)(b0 + ty + i * 8) * K1 + k0 + tx];
    __syncthreads();
    #pragma unroll
    for (int i = 0; i < 4; i++) {
        int k = k0 + ty + i * 8;
        d_xhT[(size_t)k * BB + b0 + tx] = __float2half(t32[tx][ty + i * 8]);
    }
}

__global__ void k_prep_w(const float* __restrict__ W) {
    __shared__ float t32[32][33];
    int tx = threadIdx.x, ty = threadIdx.y;
    int m0 = blockIdx.x * 32, c0 = blockIdx.y * 32;
    #pragma unroll
    for (int i = 0; i < 4; i++)
        t32[ty + i * 8][tx] = W[(size_t)(c0 + ty + i * 8) * 5120 + m0 + tx];
    __syncthreads();
    #pragma unroll
    for (int i = 0; i < 4; i++) {
        int m = m0 + ty + i * 8;
        int j = m >> 4, ii = m & 15;
        d_WTh[(size_t)j * K1 + ii * CC + c0 + tx] = __float2half(t32[tx][ty + i * 8]);
    }
}

// ---------------------------------------------------------------------------
// G1: spart[split][j][b] = sum_{k chunk} (cij[u(j),c(k)]*W[j,k]) * x[b,k]
// grid (5 j-tiles of 64, 64 splits). 8 warps (2m x 4n), warp 32j x 64b.
// 3-stage cp.async ring; A = raw W, scaled by cij in-fragment (fp32 mult).
__global__ void __launch_bounds__(256, 2) k_g1() {
    extern __shared__ __align__(16) __half sm1[];
    __half* a_s = sm1;                         // [G1STG][64*ASTR]
    __half* b_s = sm1 + G1STG * 64 * ASTR;     // [G1STG][32*BSTR]

    const int tid = threadIdx.x;
    const int j0 = blockIdx.x * 64;
    const int kbase = blockIdx.y * KCHUNK;
    const int warp = tid >> 5, lane = tid & 31;
    const int wm = warp >> 2, wn = warp & 3;
    const int m0 = wm * 32, n0 = wn * 64;
    const int lt = lane >> 3, lr = lane & 7;
    const int g = lane >> 2, t = lane & 3;

    const int u_w = (j0 >> 5) + wm;
    const float* crow = d_cij + u_w * CC;
    const int c0base = kbase % CC;             // no wrap within chunk

    const int ar = tid >> 2, aq = tid & 3;
    const __half* wrow = d_WTh + (size_t)(j0 + ar) * K1;

    const uint32_t aoff = (uint32_t)((((lt & 1) * 8 + lr) * ASTR + (lt >> 1) * 8) * 2);
    const uint32_t boff = (uint32_t)((((lt & 1) * 8 + lr) * BSTR + (lt >> 1) * 8) * 2);
    uint32_t abase[G1STG], bbase[G1STG];
    #pragma unroll
    for (int i = 0; i < G1STG; i++) {
        abase[i] = cvta_s(a_s + i * 64 * ASTR);
        bbase[i] = cvta_s(b_s + i * 32 * BSTR);
    }

    float acc[16][4];
    #pragma unroll
    for (int nb = 0; nb < 16; nb++)
        #pragma unroll
        for (int q = 0; q < 4; q++) acc[nb][q] = 0.f;

    auto issue = [&](int s) {
        int k0 = kbase + s * 32;
        int buf = s % G1STG;
        cp16(abase[buf] + (uint32_t)((ar * ASTR + aq * 8) * 2), wrow + k0 + aq * 8);
        #pragma unroll
        for (int i = 0; i < 4; i++) {
            int idx = tid + i * 256;
            int r = idx >> 5, seg = idx & 31;
            cp16(bbase[buf] + (uint32_t)((r * BSTR + seg * 8) * 2),
                 d_xhT + (size_t)(k0 + r) * BB + seg * 8);
        }
        cp_commit();
    };

    issue(0);
    issue(1);
    cp_wait1();
    __syncthreads();

    for (int s = 0; s < NSTG; s++) {
        int buf = s % G1STG;
        if (s + 2 < NSTG) issue(s + 2);

        #pragma unroll
        for (int kk = 0; kk < 32; kk += 16) {
            int cidx = c0base + s * 32 + kk;
            float2 cl = *(const float2*)(crow + cidx + 2 * t);
            float2 ch = *(const float2*)(crow + cidx + 8 + 2 * t);
            uint32_t A0[4], A1[4], rr[4];
            ldsm_x4(A0, abase[buf] + (uint32_t)((m0 * ASTR + kk) * 2) + aoff);
            ldsm_x4(A1, abase[buf] + (uint32_t)(((m0 + 16) * ASTR + kk) * 2) + aoff);
            A0[0] = scale_h2(A0[0], cl); A0[1] = scale_h2(A0[1], cl);
            A0[2] = scale_h2(A0[2], ch); A0[3] = scale_h2(A0[3], ch);
            A1[0] = scale_h2(A1[0], cl); A1[1] = scale_h2(A1[1], cl);
            A1[2] = scale_h2(A1[2], ch); A1[3] = scale_h2(A1[3], ch);
            #pragma unroll
            for (int i = 0; i < 4; i++) {
                ldsm_x4_t(rr, bbase[buf] + (uint32_t)((kk * BSTR + n0 + i * 16) * 2) + boff);
                mma16816(acc[2 * i],     A0[0], A0[1], A0[2], A0[3], rr[0], rr[1]);
                mma16816(acc[2 * i + 1], A0[0], A0[1], A0[2], A0[3], rr[2], rr[3]);
                mma16816(acc[8 + 2 * i],     A1[0], A1[1], A1[2], A1[3], rr[0], rr[1]);
                mma16816(acc[8 + 2 * i + 1], A1[0], A1[1], A1[2], A1[3], rr[2], rr[3]);
            }
        }
        if (s + 2 < NSTG) cp_wait1(); else cp_wait0();
        __syncthreads();
    }

    size_t base = (size_t)blockIdx.y * JJ * BB;
    #pragma unroll
    for (int mb = 0; mb < 2; mb++) {
        int j = j0 + m0 + mb * 16 + g;
        #pragma unroll
        for (int nb = 0; nb < 8; nb++) {
            float* a = acc[mb * 8 + nb];
            int b = n0 + nb * 8 + 2 * t;
            *(float2*)&d_spart[base + (size_t)j * BB + b] = make_float2(a[0], a[1]);
            *(float2*)&d_spart[base + (size_t)(j + 8) * BB + b] = make_float2(a[2], a[3]);
        }
    }
}

// ---------------------------------------------------------------------------
// squash: grid (32 s, 8 b-chunks of 32). 256 threads = 32 b x 8 split-slices.
__global__ void __launch_bounds__(256) k_squash(float* __restrict__ out, int final_it) {
    __shared__ float red[8][NU][33];
    int s = blockIdx.x;
    int bl = threadIdx.x & 31, h = threadIdx.x >> 5;
    int b = blockIdx.y * 32 + bl;
    #pragma unroll
    for (int u = 0; u < NU; u++) {
        size_t base = (size_t)(u * 32 + s) * BB + b;
        float v = 0.f;
        #pragma unroll
        for (int p = 0; p < 8; p++)
            v += d_spart[(size_t)(h * 8 + p) * JJ * BB + base];
        red[h][u][bl] = v;
    }
    __syncthreads();
    if (h == 0) {
        float sv[NU], q = 0.f;
        #pragma unroll
        for (int u = 0; u < NU; u++) {
            float v = 0.f;
            #pragma unroll
            for (int hh = 0; hh < 8; hh++) v += red[hh][u][bl];
            sv[u] = v;
            q = fmaf(v, v, q);
        }
        float mag = sqrtf(q);
        float f = q / ((1.f + q) * mag);
        #pragma unroll
        for (int u = 0; u < NU; u++) {
            float v = sv[u] * f;
            int j = u * 32 + s;
            if (final_it) out[b * JJ + j] = v;
            else          d_vh[j * BB + b] = __float2half(v);
        }
    }
}

// ---------------------------------------------------------------------------
// G2: A2[c,u] += sum_j W[j,k'] * (sum_b vh[j,b]*x[k',b]).
// grid (144 k'-tiles of 128, 2 b-halves of 128). 8 warps (2j x 4k').
__global__ void __launch_bounds__(256, 3) k_g2() {
    extern __shared__ __align__(16) __half sm2[];
    __half* xs = sm2;                      // [128][BSTR2]
    __half* vs = sm2 + 128 * BSTR2;        // [2][32][BSTR2]

    const int tid = threadIdx.x, warp = tid >> 5, lane = tid & 31;
    const int wm = warp >> 2, wn = warp & 3;
    const int lt = lane >> 3, lr = lane & 7;
    const int g = lane >> 2, t = lane & 3;
    const int kp0 = blockIdx.x * 128;
    const int b0 = blockIdx.y * 128;
    const int cb = kp0 % CC;

    const uint32_t xbase = cvta_s(xs);
    uint32_t vbase[2] = {cvta_s(vs), cvta_s(vs + 32 * BSTR2)};

    // vs row = 128 halfs = 16 cp16 segments; 32 rows -> 512 cp16 -> 2 iterations
    auto issueV = [&](int u, int buf) {
        #pragma unroll
        for (int i = 0; i < 2; i++) {
            int idx = tid + i * 256;
            int r = idx >> 4, seg = idx & 15;
            cp16(vbase[buf] + (uint32_t)((r * BSTR2 + seg * 8) * 2),
                 d_vh + (size_t)(u * 32 + r) * BB + b0 + seg * 8);
        }
        cp_commit();
    };

    // xs: 128 rows x 16 segs = 2048 cp16 -> 8 iterations
    #pragma unroll
    for (int i = 0; i < 8; i++) {
        int idx = tid + i * 256;
        int r = idx >> 4, seg = idx & 15;
        cp16(xbase + (uint32_t)((r * BSTR2 + seg * 8) * 2),
             d_xhT + (size_t)(kp0 + r) * BB + b0 + seg * 8);
    }
    issueV(0, 0);
    cp_wait0();
    __syncthreads();

    const uint32_t aoff = (uint32_t)(((wm * 16 + (lt & 1) * 8 + lr) * BSTR2 + (lt >> 1) * 8) * 2);
    const uint32_t boffc = (uint32_t)((((lt >> 1) * 8 + lr) * BSTR2 + (lt & 1) * 8) * 2);

    for (int u = 0; u < NU; u++) {
        int buf = u & 1;
        if (u + 1 < NU) issueV(u + 1, buf ^ 1);

        float acc[4][4];
        #pragma unroll
        for (int nb = 0; nb < 4; nb++)
            #pragma unroll
            for (int q = 0; q < 4; q++) acc[nb][q] = 0.f;

        #pragma unroll
        for (int kk = 0; kk < 128; kk += 16) {
            uint32_t A[4], rr[4];
            ldsm_x4(A, vbase[buf] + (uint32_t)(kk * 2) + aoff);
            #pragma unroll
            for (int q = 0; q < 2; q++) {
                ldsm_x4(rr, xbase + (uint32_t)(((wn * 32 + q * 16) * BSTR2 + kk) * 2) + boffc);
                mma16816(acc[2 * q],     A[0], A[1], A[2], A[3], rr[0], rr[1]);
                mma16816(acc[2 * q + 1], A[0], A[1], A[2], A[3], rr[2], rr[3]);
            }
        }

        int jA = u * 32 + wm * 16 + g;
        const __half* wrow = d_WTh + (size_t)jA * K1;
        #pragma unroll
        for (int nb = 0; nb < 4; nb++) {
            int kc = kp0 + wn * 32 + nb * 8 + 2 * t;
            float2 w0 = __half22float2(*(const __half2*)(wrow + kc));
            float2 w1 = __half22float2(*(const __half2*)(wrow + 8 * (size_t)K1 + kc));
            float p0 = acc[nb][0] * w0.x + acc[nb][2] * w1.x;
            float p1 = acc[nb][1] * w0.y + acc[nb][3] * w1.y;
            #pragma unroll
            for (int m = 4; m <= 16; m <<= 1) {
                p0 += __shfl_xor_sync(0xffffffffu, p0, m);
                p1 += __shfl_xor_sync(0xffffffffu, p1, m);
            }
            if (g == 0) {
                int cc = cb + wn * 32 + nb * 8 + 2 * t;
                atomicAdd(&d_A2[cc * NU + u], p0);
                atomicAdd(&d_A2[(cc + 1) * NU + u], p1);
            }
        }
        if (u + 1 < NU) cp_wait0();
        __syncthreads();
    }
}

// ---------------------------------------------------------------------------
__global__ void k_bupd() {
    int c = blockIdx.x * blockDim.x + threadIdx.x;
    if (c >= CC) return;
    float bv[NU], m = -1e30f;
    #pragma unroll
    for (int u = 0; u < NU; u++) {
        float a = d_A2[c * NU + u];
        d_A2[c * NU + u] = 0.f;
        float nb = d_bij[c * NU + u] + a * (1.f / BB);
        d_bij[c * NU + u] = nb;
        bv[u] = nb;
        m = fmaxf(m, nb);
    }
    float den = 0.f;
    #pragma unroll
    for (int u = 0; u < NU; u++) { bv[u] = expf(bv[u] - m); den += bv[u]; }
    float inv = 1.f / den;
    #pragma unroll
    for (int u = 0; u < NU; u++) d_cij[u * CC + c] = bv[u] * inv;
}

// ---------------------------------------------------------------------------
#define G1_SMEM ((G1STG * 64 * ASTR + G1STG * 32 * BSTR) * 2)   // 66048
#define G2_SMEM ((128 * BSTR2 + 64 * BSTR2) * 2)                // 52224

extern "C" void kernel_launch(void* const* d_in, const int* in_sizes, int n_in,
                              void* d_out, int out_size) {
    const float* x = (const float*)d_in[0];
    const float* W = (const float*)d_in[1];
    if (n_in >= 2 && in_sizes[0] == CC * NU * SS * 16 && in_sizes[1] == BB * 16 * CC) {
        const float* tmp = x; x = W; W = tmp;
    }
    float* out = (float*)d_out;

    static int attr_done = 0;
    if (!attr_done) {
        cudaFuncSetAttribute(k_g1, cudaFuncAttributeMaxDynamicSharedMemorySize, G1_SMEM);
        cudaFuncSetAttribute(k_g2, cudaFuncAttributeMaxDynamicSharedMemorySize, G2_SMEM);
        attr_done = 1;
    }

    k_prep_init<<<(CC * NU + 255) / 256, 256>>>();
    k_prep_x<<<dim3(K1 / 32, BB / 32), dim3(32, 8)>>>(x);
    k_prep_w<<<dim3(5120 / 32, CC / 32), dim3(32, 8)>>>(W);

    for (int it = 0; it < 3; it++) {
        k_g1<<<dim3(5, SPLIT), 256, G1_SMEM>>>();
        k_squash<<<dim3(SS, 8), 256>>>(out, it == 2);
        if (it < 2) {
            k_g2<<<dim3(K1 / 128, 2), 256, G2_SMEM>>>();
            k_bupd<<<(CC + 255) / 256, 256>>>();
        }
    }
}

// round 8
// speedup vs baseline: 3.7943x; 1.1276x over previous
#include <cuda_runtime.h>
#include <cuda_fp16.h>
#include <stdint.h>

// CapsuleLayer dynamic routing: recompute architecture, pipelined HMMA GEMMs.
// B=256, I=16, C=1152, U=10, S=32, J=320, K1=18432, 3 iterations.

#define BB   256
#define CC   1152
#define NU   10
#define SS   32
#define JJ   320
#define K1   18432
#define SPLIT 48
#define KCHUNK 384          // K1/SPLIT
#define NSTG  12            // KCHUNK/32
#define G1STG 3             // pipeline depth
#define ASTR  40            // A smem stride (halfs)
#define BSTR  264           // B smem stride (halfs)
#define BSTR2 136           // G2 smem stride (halfs), 128 data + pad

// ---- static device scratch ----
__device__ __half d_xhT[(size_t)K1 * BB];            // 9.4 MB  [k][b]
__device__ __half d_WTh[(size_t)JJ * K1];            // 11.8 MB [j][k] fp16, k=i*1152+c
__device__ float  d_spart[(size_t)SPLIT * JJ * BB];  // 15.7 MB
__device__ __half d_vh [JJ * BB];                    // [j][b]
__device__ float  d_bij[CC * NU];
__device__ __half d_cijh[NU * CC];                   // [u][c] fp16
__device__ float  d_A2 [CC * NU];

// ---- helpers ----
__device__ __forceinline__ void mma16816(float* d, uint32_t a0, uint32_t a1,
                                         uint32_t a2, uint32_t a3,
                                         uint32_t b0, uint32_t b1) {
    asm volatile(
        "mma.sync.aligned.m16n8k16.row.col.f32.f16.f16.f32 "
        "{%0,%1,%2,%3},{%4,%5,%6,%7},{%8,%9},{%0,%1,%2,%3};"
        : "+f"(d[0]), "+f"(d[1]), "+f"(d[2]), "+f"(d[3])
        : "r"(a0), "r"(a1), "r"(a2), "r"(a3), "r"(b0), "r"(b1));
}
__device__ __forceinline__ uint32_t cvta_s(const void* p) {
    return (uint32_t)__cvta_generic_to_shared(p);
}
__device__ __forceinline__ void ldsm_x4(uint32_t* r, uint32_t addr) {
    asm volatile("ldmatrix.sync.aligned.m8n8.x4.shared.b16 {%0,%1,%2,%3},[%4];"
                 : "=r"(r[0]), "=r"(r[1]), "=r"(r[2]), "=r"(r[3]) : "r"(addr));
}
__device__ __forceinline__ void ldsm_x4_t(uint32_t* r, uint32_t addr) {
    asm volatile("ldmatrix.sync.aligned.m8n8.x4.trans.shared.b16 {%0,%1,%2,%3},[%4];"
                 : "=r"(r[0]), "=r"(r[1]), "=r"(r[2]), "=r"(r[3]) : "r"(addr));
}
__device__ __forceinline__ uint32_t h2u(__half2 h) {
    return *reinterpret_cast<uint32_t*>(&h);
}
__device__ __forceinline__ uint32_t hmul2u(uint32_t a, uint32_t b) {
    __half2 r = __hmul2(*reinterpret_cast<__half2*>(&a), *reinterpret_cast<__half2*>(&b));
    return h2u(r);
}
__device__ __forceinline__ void cp16(uint32_t dst, const void* src) {
    asm volatile("cp.async.cg.shared.global [%0], [%1], 16;" :: "r"(dst), "l"(src));
}
__device__ __forceinline__ void cp_commit() { asm volatile("cp.async.commit_group;"); }
__device__ __forceinline__ void cp_wait0() { asm volatile("cp.async.wait_group 0;"); }
__device__ __forceinline__ void cp_wait1() { asm volatile("cp.async.wait_group 1;"); }

// ---------------------------------------------------------------------------
__global__ void k_prep_init() {
    int t = blockIdx.x * blockDim.x + threadIdx.x;
    if (t < CC * NU) {
        d_bij[t] = 0.f; d_A2[t] = 0.f;
        d_cijh[t] = __float2half(0.1f);
    }
}

__global__ void k_prep_x(const float* __restrict__ x) {
    __shared__ float t32[32][33];
    int tx = threadIdx.x, ty = threadIdx.y;
    int k0 = blockIdx.x * 32, b0 = blockIdx.y * 32;
    #pragma unroll
    for (int i = 0; i < 4; i++)
        t32[ty + i * 8][tx] = x[(size_t)(b0 + ty + i * 8) * K1 + k0 + tx];
    __syncthreads();
    #pragma unroll
    for (int i = 0; i < 4; i++) {
        int k = k0 + ty + i * 8;
        d_xhT[(size_t)k * BB + b0 + tx] = __float2half(t32[tx][ty + i * 8]);
    }
}

__global__ void k_prep_w(const float* __restrict__ W) {
    __shared__ float t32[32][33];
    int tx = threadIdx.x, ty = threadIdx.y;
    int m0 = blockIdx.x * 32, c0 = blockIdx.y * 32;
    #pragma unroll
    for (int i = 0; i < 4; i++)
        t32[ty + i * 8][tx] = W[(size_t)(c0 + ty + i * 8) * 5120 + m0 + tx];
    __syncthreads();
    #pragma unroll
    for (int i = 0; i < 4; i++) {
        int m = m0 + ty + i * 8;
        int j = m >> 4, ii = m & 15;
        d_WTh[(size_t)j * K1 + ii * CC + c0 + tx] = __float2half(t32[tx][ty + i * 8]);
    }
}

// ---------------------------------------------------------------------------
// G1: spart[split][j][b] = sum_{k chunk} (cij[u(j),c(k)]*W[j,k]) * x[b,k]
// grid (5 j-tiles of 64, 48 splits) = 240 blocks (single wave at 2 CTA/SM).
// 3-stage cp.async ring; A = raw W, scaled by fp16 cij via HMUL2 in-fragment.
__global__ void __launch_bounds__(256, 2) k_g1() {
    extern __shared__ __align__(16) __half sm1[];
    __half* a_s = sm1;                         // [G1STG][64*ASTR]
    __half* b_s = sm1 + G1STG * 64 * ASTR;     // [G1STG][32*BSTR]

    const int tid = threadIdx.x;
    const int j0 = blockIdx.x * 64;
    const int kbase = blockIdx.y * KCHUNK;
    const int warp = tid >> 5, lane = tid & 31;
    const int wm = warp >> 2, wn = warp & 3;
    const int m0 = wm * 32, n0 = wn * 64;
    const int lt = lane >> 3, lr = lane & 7;
    const int g = lane >> 2, t = lane & 3;

    const int u_w = (j0 >> 5) + wm;
    const __half* crow = d_cijh + u_w * CC;
    const int c0base = kbase % CC;             // no wrap within chunk (384 | 1152)

    const int ar = tid >> 2, aq = tid & 3;
    const __half* wrow = d_WTh + (size_t)(j0 + ar) * K1;

    const uint32_t aoff = (uint32_t)((((lt & 1) * 8 + lr) * ASTR + (lt >> 1) * 8) * 2);
    const uint32_t boff = (uint32_t)((((lt & 1) * 8 + lr) * BSTR + (lt >> 1) * 8) * 2);
    uint32_t abase[G1STG], bbase[G1STG];
    #pragma unroll
    for (int i = 0; i < G1STG; i++) {
        abase[i] = cvta_s(a_s + i * 64 * ASTR);
        bbase[i] = cvta_s(b_s + i * 32 * BSTR);
    }

    float acc[16][4];
    #pragma unroll
    for (int nb = 0; nb < 16; nb++)
        #pragma unroll
        for (int q = 0; q < 4; q++) acc[nb][q] = 0.f;

    auto issue = [&](int s) {
        int k0 = kbase + s * 32;
        int buf = s % G1STG;
        cp16(abase[buf] + (uint32_t)((ar * ASTR + aq * 8) * 2), wrow + k0 + aq * 8);
        #pragma unroll
        for (int i = 0; i < 4; i++) {
            int idx = tid + i * 256;
            int r = idx >> 5, seg = idx & 31;
            cp16(bbase[buf] + (uint32_t)((r * BSTR + seg * 8) * 2),
                 d_xhT + (size_t)(k0 + r) * BB + seg * 8);
        }
        cp_commit();
    };

    issue(0);
    issue(1);
    cp_wait1();
    __syncthreads();

    for (int s = 0; s < NSTG; s++) {
        int buf = s % G1STG;
        if (s + 2 < NSTG) issue(s + 2);

        #pragma unroll
        for (int kk = 0; kk < 32; kk += 16) {
            int cidx = c0base + s * 32 + kk;
            uint32_t cl = *(const uint32_t*)(crow + cidx + 2 * t);
            uint32_t ch = *(const uint32_t*)(crow + cidx + 8 + 2 * t);
            uint32_t A0[4], A1[4], rr[4];
            ldsm_x4(A0, abase[buf] + (uint32_t)((m0 * ASTR + kk) * 2) + aoff);
            ldsm_x4(A1, abase[buf] + (uint32_t)(((m0 + 16) * ASTR + kk) * 2) + aoff);
            A0[0] = hmul2u(A0[0], cl); A0[1] = hmul2u(A0[1], cl);
            A0[2] = hmul2u(A0[2], ch); A0[3] = hmul2u(A0[3], ch);
            A1[0] = hmul2u(A1[0], cl); A1[1] = hmul2u(A1[1], cl);
            A1[2] = hmul2u(A1[2], ch); A1[3] = hmul2u(A1[3], ch);
            #pragma unroll
            for (int i = 0; i < 4; i++) {
                ldsm_x4_t(rr, bbase[buf] + (uint32_t)((kk * BSTR + n0 + i * 16) * 2) + boff);
                mma16816(acc[2 * i],     A0[0], A0[1], A0[2], A0[3], rr[0], rr[1]);
                mma16816(acc[2 * i + 1], A0[0], A0[1], A0[2], A0[3], rr[2], rr[3]);
                mma16816(acc[8 + 2 * i],     A1[0], A1[1], A1[2], A1[3], rr[0], rr[1]);
                mma16816(acc[8 + 2 * i + 1], A1[0], A1[1], A1[2], A1[3], rr[2], rr[3]);
            }
        }
        if (s + 2 < NSTG) cp_wait1(); else cp_wait0();
        __syncthreads();
    }

    size_t base = (size_t)blockIdx.y * JJ * BB;
    #pragma unroll
    for (int mb = 0; mb < 2; mb++) {
        int j = j0 + m0 + mb * 16 + g;
        #pragma unroll
        for (int nb = 0; nb < 8; nb++) {
            float* a = acc[mb * 8 + nb];
            int b = n0 + nb * 8 + 2 * t;
            *(float2*)&d_spart[base + (size_t)j * BB + b] = make_float2(a[0], a[1]);
            *(float2*)&d_spart[base + (size_t)(j + 8) * BB + b] = make_float2(a[2], a[3]);
        }
    }
}

// ---------------------------------------------------------------------------
// squash: grid (32 s, 8 b-chunks of 32). 256 threads = 32 b x 8 split-slices.
__global__ void __launch_bounds__(256) k_squash(float* __restrict__ out, int final_it) {
    __shared__ float red[8][NU][33];
    int s = blockIdx.x;
    int bl = threadIdx.x & 31, h = threadIdx.x >> 5;
    int b = blockIdx.y * 32 + bl;
    #pragma unroll
    for (int u = 0; u < NU; u++) {
        size_t base = (size_t)(u * 32 + s) * BB + b;
        float v = 0.f;
        #pragma unroll
        for (int p = 0; p < 6; p++)
            v += d_spart[(size_t)(h * 6 + p) * JJ * BB + base];
        red[h][u][bl] = v;
    }
    __syncthreads();
    if (h == 0) {
        float sv[NU], q = 0.f;
        #pragma unroll
        for (int u = 0; u < NU; u++) {
            float v = 0.f;
            #pragma unroll
            for (int hh = 0; hh < 8; hh++) v += red[hh][u][bl];
            sv[u] = v;
            q = fmaf(v, v, q);
        }
        float mag = sqrtf(q);
        float f = q / ((1.f + q) * mag);
        #pragma unroll
        for (int u = 0; u < NU; u++) {
            float v = sv[u] * f;
            int j = u * 32 + s;
            if (final_it) out[b * JJ + j] = v;
            else          d_vh[j * BB + b] = __float2half(v);
        }
    }
}

// ---------------------------------------------------------------------------
// G2: A2[c,u] += sum_j W[j,k'] * (sum_b vh[j,b]*x[k',b]).
// grid (144 k'-tiles of 128, 2 b-halves of 128). 8 warps (2j x 4k').
__global__ void __launch_bounds__(256, 3) k_g2() {
    extern __shared__ __align__(16) __half sm2[];
    __half* xs = sm2;                      // [128][BSTR2]
    __half* vs = sm2 + 128 * BSTR2;        // [2][32][BSTR2]

    const int tid = threadIdx.x, warp = tid >> 5, lane = tid & 31;
    const int wm = warp >> 2, wn = warp & 3;
    const int lt = lane >> 3, lr = lane & 7;
    const int g = lane >> 2, t = lane & 3;
    const int kp0 = blockIdx.x * 128;
    const int b0 = blockIdx.y * 128;
    const int cb = kp0 % CC;

    const uint32_t xbase = cvta_s(xs);
    uint32_t vbase[2] = {cvta_s(vs), cvta_s(vs + 32 * BSTR2)};

    auto issueV = [&](int u, int buf) {
        #pragma unroll
        for (int i = 0; i < 2; i++) {
            int idx = tid + i * 256;
            int r = idx >> 4, seg = idx & 15;
            cp16(vbase[buf] + (uint32_t)((r * BSTR2 + seg * 8) * 2),
                 d_vh + (size_t)(u * 32 + r) * BB + b0 + seg * 8);
        }
        cp_commit();
    };

    #pragma unroll
    for (int i = 0; i < 8; i++) {
        int idx = tid + i * 256;
        int r = idx >> 4, seg = idx & 15;
        cp16(xbase + (uint32_t)((r * BSTR2 + seg * 8) * 2),
             d_xhT + (size_t)(kp0 + r) * BB + b0 + seg * 8);
    }
    issueV(0, 0);
    cp_wait0();
    __syncthreads();

    const uint32_t aoff = (uint32_t)(((wm * 16 + (lt & 1) * 8 + lr) * BSTR2 + (lt >> 1) * 8) * 2);
    const uint32_t boffc = (uint32_t)((((lt >> 1) * 8 + lr) * BSTR2 + (lt & 1) * 8) * 2);

    for (int u = 0; u < NU; u++) {
        int buf = u & 1;
        if (u + 1 < NU) issueV(u + 1, buf ^ 1);

        float acc[4][4];
        #pragma unroll
        for (int nb = 0; nb < 4; nb++)
            #pragma unroll
            for (int q = 0; q < 4; q++) acc[nb][q] = 0.f;

        #pragma unroll
        for (int kk = 0; kk < 128; kk += 16) {
            uint32_t A[4], rr[4];
            ldsm_x4(A, vbase[buf] + (uint32_t)(kk * 2) + aoff);
            #pragma unroll
            for (int q = 0; q < 2; q++) {
                ldsm_x4(rr, xbase + (uint32_t)(((wn * 32 + q * 16) * BSTR2 + kk) * 2) + boffc);
                mma16816(acc[2 * q],     A[0], A[1], A[2], A[3], rr[0], rr[1]);
                mma16816(acc[2 * q + 1], A[0], A[1], A[2], A[3], rr[2], rr[3]);
            }
        }

        int jA = u * 32 + wm * 16 + g;
        const __half* wrow = d_WTh + (size_t)jA * K1;
        #pragma unroll
        for (int nb = 0; nb < 4; nb++) {
            int kc = kp0 + wn * 32 + nb * 8 + 2 * t;
            float2 w0 = __half22float2(*(const __half2*)(wrow + kc));
            float2 w1 = __half22float2(*(const __half2*)(wrow + 8 * (size_t)K1 + kc));
            float p0 = acc[nb][0] * w0.x + acc[nb][2] * w1.x;
            float p1 = acc[nb][1] * w0.y + acc[nb][3] * w1.y;
            #pragma unroll
            for (int m = 4; m <= 16; m <<= 1) {
                p0 += __shfl_xor_sync(0xffffffffu, p0, m);
                p1 += __shfl_xor_sync(0xffffffffu, p1, m);
            }
            if (g == 0) {
                int cc = cb + wn * 32 + nb * 8 + 2 * t;
                atomicAdd(&d_A2[cc * NU + u], p0);
                atomicAdd(&d_A2[(cc + 1) * NU + u], p1);
            }
        }
        if (u + 1 < NU) cp_wait0();
        __syncthreads();
    }
}

// ---------------------------------------------------------------------------
__global__ void k_bupd() {
    int c = blockIdx.x * blockDim.x + threadIdx.x;
    if (c >= CC) return;
    float bv[NU], m = -1e30f;
    #pragma unroll
    for (int u = 0; u < NU; u++) {
        float a = d_A2[c * NU + u];
        d_A2[c * NU + u] = 0.f;
        float nb = d_bij[c * NU + u] + a * (1.f / BB);
        d_bij[c * NU + u] = nb;
        bv[u] = nb;
        m = fmaxf(m, nb);
    }
    float den = 0.f;
    #pragma unroll
    for (int u = 0; u < NU; u++) { bv[u] = expf(bv[u] - m); den += bv[u]; }
    float inv = 1.f / den;
    #pragma unroll
    for (int u = 0; u < NU; u++) d_cijh[u * CC + c] = __float2half(bv[u] * inv);
}

// ---------------------------------------------------------------------------
#define G1_SMEM ((G1STG * 64 * ASTR + G1STG * 32 * BSTR) * 2)   // 66048
#define G2_SMEM ((128 * BSTR2 + 64 * BSTR2) * 2)                // 52224

extern "C" void kernel_launch(void* const* d_in, const int* in_sizes, int n_in,
                              void* d_out, int out_size) {
    const float* x = (const float*)d_in[0];
    const float* W = (const float*)d_in[1];
    if (n_in >= 2 && in_sizes[0] == CC * NU * SS * 16 && in_sizes[1] == BB * 16 * CC) {
        const float* tmp = x; x = W; W = tmp;
    }
    float* out = (float*)d_out;

    static int attr_done = 0;
    if (!attr_done) {
        cudaFuncSetAttribute(k_g1, cudaFuncAttributeMaxDynamicSharedMemorySize, G1_SMEM);
        cudaFuncSetAttribute(k_g2, cudaFuncAttributeMaxDynamicSharedMemorySize, G2_SMEM);
        attr_done = 1;
    }

    k_prep_init<<<(CC * NU + 255) / 256, 256>>>();
    k_prep_x<<<dim3(K1 / 32, BB / 32), dim3(32, 8)>>>(x);
    k_prep_w<<<dim3(5120 / 32, CC / 32), dim3(32, 8)>>>(W);

    for (int it = 0; it < 3; it++) {
        k_g1<<<dim3(5, SPLIT), 256, G1_SMEM>>>();
        k_squash<<<dim3(SS, 8), 256>>>(out, it == 2);
        if (it < 2) {
            k_g2<<<dim3(K1 / 128, 2), 256, G2_SMEM>>>();
            k_bupd<<<(CC + 255) / 256, 256>>>();
        }
    }
}